// round 13
// baseline (speedup 1.0000x reference)
#include <cuda_runtime.h>
#include <stdint.h>

// Problem shapes (fixed by the dataset).
#define BB 64
#define PP 2048
#define GG 512
#define NZ 16
#define GH (GG / NZ)    // 32 gts per tile

// Merged best per (image, pred): (iou_bits<<32) | (511 - g). Zero-initialized;
// K2 resets each element after consuming it (replay-safe).
__device__ unsigned long long g_best[BB * PP];
__device__ float g_ap[BB];
__device__ unsigned int g_ticket;   // zero-init; self-resetting via atomicInc wrap

// ---------------------------------------------------------------------------
// K1: per (image, pred, gt-tile) first-max argmax_g IoU + exact max value,
// merged globally via u64 atomicMax (iou desc, tie -> lower g).
// 256 threads, 2 preds/thread, 32 gts in smem. grid = (PP/512, BB, NZ).
// best init 0: negative ious (unclamped iw) never update; all-nonpositive
// tiles pack (0, tile-g0) and the global merge resolves them to g = 0,
// matching the reference argmax of an all-zero row (cand=false there anyway).
// ---------------------------------------------------------------------------
__global__ __launch_bounds__(256) void k_bestiou(
    const float* __restrict__ pred_boxes,   // [B,P,4] xywh
    const float* __restrict__ gt_boxes)     // [B,G,4] xywh
{
    const int b  = blockIdx.y;
    const int zt = blockIdx.z;
    const int p0 = blockIdx.x * 512 + threadIdx.x;
    const int p1 = p0 + 256;

    __shared__ float4 sbox[GH];   // x1,y1,x2,y2
    __shared__ float  sarea[GH];  // exact area

    const float4* gbp = reinterpret_cast<const float4*>(
        gt_boxes + ((size_t)b * GG + (size_t)zt * GH) * 4);
    if (threadIdx.x < GH) {
        float4 v = gbp[threadIdx.x];
        float x2 = v.x + v.z;
        float y2 = v.y + v.w;
        sbox[threadIdx.x]  = make_float4(v.x, v.y, x2, y2);
        sarea[threadIdx.x] = fabsf((x2 - v.x) * (y2 - v.y));
    }
    __syncthreads();

    const float4* pbp = reinterpret_cast<const float4*>(pred_boxes + (size_t)b * PP * 4);
    float4 q0 = pbp[p0];
    float4 q1 = pbp[p1];
    const float ax1 = q0.x, ay1 = q0.y, ax2 = q0.x + q0.z, ay2 = q0.y + q0.w;
    const float bx1 = q1.x, by1 = q1.y, bx2 = q1.x + q1.z, by2 = q1.y + q1.w;
    const float apa = fabsf((ax2 - ax1) * (ay2 - ay1)) + 1e-9f;  // area + eps hoisted
    const float bpa = fabsf((bx2 - bx1) * (by2 - by1)) + 1e-9f;

    float best0 = 0.0f, best1 = 0.0f;
    int   bg0 = 0, bg1 = 0;

#pragma unroll
    for (int g = 0; g < GH; ++g) {
        float4 gb = sbox[g];
        float  sa = sarea[g];
        {
            float iw = fminf(ax2, gb.z) - fmaxf(ax1, gb.x);   // unclamped
            float ih = fmaxf(fminf(ay2, gb.w) - fmaxf(ay1, gb.y), 0.0f);
            float n  = iw * ih;
            float u  = (apa + sa) - n;                        // >= eps, NaN-free
            float iou = __fdividef(n, u);
            if (iou > best0) { best0 = iou; bg0 = g; }        // strict > = first max
        }
        {
            float iw = fminf(bx2, gb.z) - fmaxf(bx1, gb.x);
            float ih = fmaxf(fminf(by2, gb.w) - fmaxf(by1, gb.y), 0.0f);
            float n  = iw * ih;
            float u  = (bpa + sa) - n;
            float iou = __fdividef(n, u);
            if (iou > best1) { best1 = iou; bg1 = g; }
        }
    }

    const int goff = zt * GH;
    {
        unsigned long long pack = ((unsigned long long)__float_as_uint(best0) << 32)
                                | (unsigned)(511 - (bg0 + goff));
        atomicMax(&g_best[(size_t)b * PP + p0], pack);
    }
    {
        unsigned long long pack = ((unsigned long long)__float_as_uint(best1) << 32)
                                | (unsigned)(511 - (bg1 + goff));
        atomicMax(&g_best[(size_t)b * PP + p1], pack);
    }
}

// ---------------------------------------------------------------------------
// K2 (fused): one block per image, 512 threads, 4 preds/thread.
//  1. consume g_best (+reset for next replay), detect candidates
//  2. exact stable-sort rank for candidates only (warp-cooperative count)
//  3. in-block compaction (deterministic tid-order; TP/AP are pairwise on
//     unique (rank,ginv) keys, so compaction order is semantically irrelevant)
//  4. greedy TP + AP; last block (ticket) computes the batch mean.
// ---------------------------------------------------------------------------
__global__ __launch_bounds__(512) void k_ap(
    const float* __restrict__ pred_scores,   // [B,P]
    const int*   __restrict__ pred_classes,  // [B,P]
    const int*   __restrict__ gt_classes,    // [B,G]
    float* __restrict__ out)
{
    const int b   = blockIdx.x;
    const int tid = threadIdx.x;
    const int lane = tid & 31, wid = tid >> 5;

    __shared__ float         ssc[PP];     // all scores of image b
    __shared__ unsigned int  scomp[PP];   // compacted (rank<<9)|ginv
    __shared__ unsigned char stp[PP];
    __shared__ int   wsum[16];
    __shared__ float wred[16];

    const float4* sp = reinterpret_cast<const float4*>(pred_scores + (size_t)b * PP);
    for (int i = tid; i < PP / 4; i += 512)
        reinterpret_cast<float4*>(ssc)[i] = sp[i];
    __syncthreads();

    const unsigned full = 0xFFFFFFFFu;

    // Per-thread candidates (4 preds: tid + k*512), with exact ranks.
    unsigned int vals[4];
    int c = 0;
#pragma unroll
    for (int k = 0; k < 4; ++k) {
        const int p = tid + k * 512;
        const size_t idx = (size_t)b * PP + p;
        unsigned long long v = g_best[idx];
        g_best[idx] = 0ULL;   // reset for next replay (sole reader)

        const int   ginv = (int)(v & 0x1FF);
        const int   g    = 511 - ginv;
        const float biou = __uint_as_float((unsigned int)(v >> 32));
        const bool  cand = (biou > 0.5f) &&
                           (pred_classes[idx] == gt_classes[(size_t)b * GG + g]);
        const float ms = ssc[p];

        unsigned int res = 0xFFFFFFFFu;
        unsigned bal = __ballot_sync(full, cand);
        while (bal) {
            int src = __ffs(bal) - 1;
            bal &= bal - 1;
            int   pc = __shfl_sync(full, p,  src);
            float sc = __shfl_sync(full, ms, src);
            int cnt = 0;
            // rank = #(q: score_q > score_p || (score_q == score_p && q < p))
            for (int q = lane; q < PP; q += 32) {
                float sq = ssc[q];
                cnt += (sq > sc) || (sq == sc && q < pc);
            }
            cnt = __reduce_add_sync(full, cnt);
            if (lane == src) res = ((unsigned int)cnt << 9) | (unsigned int)ginv;
        }
        vals[k] = cand ? res : 0xFFFFFFFFu;
        c += cand ? 1 : 0;
    }

    // Block scan of per-thread counts -> deterministic compaction offsets.
    int sc = c;
    for (int o = 1; o < 32; o <<= 1) {
        int u = __shfl_up_sync(full, sc, o);
        if (lane >= o) sc += u;
    }
    if (lane == 31) wsum[wid] = sc;
    __syncthreads();
    if (wid == 0 && lane < 16) {
        int u = wsum[lane];
        for (int o = 1; o < 16; o <<= 1) {
            int w = __shfl_up_sync(0xFFFFu, u, o);
            if (lane >= o) u += w;
        }
        wsum[lane] = u;
    }
    __syncthreads();
    int off = (sc - c) + (wid > 0 ? wsum[wid - 1] : 0);
    const int n = wsum[15];
#pragma unroll
    for (int k = 0; k < 4; ++k)
        if (vals[k] != 0xFFFFFFFFu) scomp[off++] = vals[k];
    __syncthreads();

    // TP iff no other candidate with same gt and smaller rank.
    // packed = (rank<<9)|ginv: same ginv -> same gt; smaller packed -> smaller rank.
    for (int i = tid; i < n; i += 512) {
        unsigned int v = scomp[i];
        int tp = 1;
        for (int j = 0; j < n; ++j) {
            unsigned int w = scomp[j];
            if (w < v && !((w ^ v) & 0x1FFu)) tp = 0;
        }
        stp[i] = (unsigned char)tp;
    }
    __syncthreads();

    // AP terms. For a tp at global rank r (k = r+1), j = 1 + #(tps with rank < r):
    //   term = 0.5 * ( j/k + (k==1 ? 1 : (j-1)/(k-1)) );  AP = sum(term)/G.
    float acc = 0.0f;
    for (int i = tid; i < n; i += 512) {
        if (!stp[i]) continue;
        unsigned int v = scomp[i];
        unsigned int r = v >> 9;
        int j = 1;
        for (int m = 0; m < n; ++m)
            j += (stp[m] && (scomp[m] >> 9) < r) ? 1 : 0;
        float kk = (float)(r + 1);
        float pj = (float)j;
        float prev = (r == 0) ? 1.0f : (pj - 1.0f) / (kk - 1.0f);
        acc += 0.5f * (pj / kk + prev);
    }

    // Deterministic block reduce.
    for (int o = 16; o > 0; o >>= 1) acc += __shfl_down_sync(full, acc, o);
    if (lane == 0) wred[wid] = acc;
    __syncthreads();
    if (tid == 0) {
        float u = 0.0f;
#pragma unroll
        for (int w = 0; w < 16; ++w) u += wred[w];
        g_ap[b] = u / (float)GG;

        // Ticket: last block computes the mean. atomicInc wraps 63 -> 0, so the
        // counter self-resets for every graph replay.
        __threadfence();
        unsigned old = atomicInc(&g_ticket, BB - 1);
        if (old == BB - 1) {
            float s = 0.0f;
#pragma unroll
            for (int i = 0; i < BB; ++i) s += g_ap[i];   // fixed order
            out[0] = s * (1.0f / (float)BB);
        }
    }
}

// ---------------------------------------------------------------------------
extern "C" void kernel_launch(void* const* d_in, const int* in_sizes, int n_in,
                              void* d_out, int out_size)
{
    const float* pred_boxes   = (const float*)d_in[0];
    const float* pred_scores  = (const float*)d_in[1];
    const int*   pred_classes = (const int*)d_in[2];
    const float* gt_boxes     = (const float*)d_in[3];
    const int*   gt_classes   = (const int*)d_in[4];
    float* out = (float*)d_out;

    dim3 g1(PP / 512, BB, NZ);
    k_bestiou<<<g1, 256>>>(pred_boxes, gt_boxes);
    k_ap<<<BB, 512>>>(pred_scores, pred_classes, gt_classes, out);
}

// round 14
// speedup vs baseline: 1.0676x; 1.0676x over previous
#include <cuda_runtime.h>
#include <stdint.h>

// Problem shapes (fixed by the dataset).
#define BB 64
#define PP 2048
#define GG 512
#define NZ 16
#define GH (GG / NZ)    // 32 gts per tile

// Merged best per (image, pred): (iou_bits<<32) | (511 - g). Zero-initialized;
// K2a resets each element after consuming it (replay-safe).
__device__ unsigned long long g_best[BB * PP];
// Dense per (image, pred): (rank<<9) | ginv. 0xFFFFFFFF = not a candidate.
__device__ unsigned int g_cand[BB * PP];
__device__ float g_ap[BB];
__device__ unsigned int g_ticket;   // zero-init; self-resetting via atomicInc wrap

// ---------------------------------------------------------------------------
// K1 (round-13 formulation, measured ~42us — unchanged):
// per (image, pred, gt-tile) first-max argmax_g IoU + exact max value,
// merged globally via u64 atomicMax (iou desc, tie -> lower g).
// 256 threads, 2 preds/thread, 32 gts in smem. grid = (PP/512, BB, NZ).
// best init 0: negative ious (unclamped iw) never update; all-nonpositive
// tiles pack (0, tile-g0) and the global merge resolves them to g = 0,
// matching the reference argmax of an all-zero row (cand=false there anyway).
// ---------------------------------------------------------------------------
__global__ __launch_bounds__(256) void k_bestiou(
    const float* __restrict__ pred_boxes,   // [B,P,4] xywh
    const float* __restrict__ gt_boxes)     // [B,G,4] xywh
{
    const int b  = blockIdx.y;
    const int zt = blockIdx.z;
    const int p0 = blockIdx.x * 512 + threadIdx.x;
    const int p1 = p0 + 256;

    __shared__ float4 sbox[GH];   // x1,y1,x2,y2
    __shared__ float  sarea[GH];  // exact area

    const float4* gbp = reinterpret_cast<const float4*>(
        gt_boxes + ((size_t)b * GG + (size_t)zt * GH) * 4);
    if (threadIdx.x < GH) {
        float4 v = gbp[threadIdx.x];
        float x2 = v.x + v.z;
        float y2 = v.y + v.w;
        sbox[threadIdx.x]  = make_float4(v.x, v.y, x2, y2);
        sarea[threadIdx.x] = fabsf((x2 - v.x) * (y2 - v.y));
    }
    __syncthreads();

    const float4* pbp = reinterpret_cast<const float4*>(pred_boxes + (size_t)b * PP * 4);
    float4 q0 = pbp[p0];
    float4 q1 = pbp[p1];
    const float ax1 = q0.x, ay1 = q0.y, ax2 = q0.x + q0.z, ay2 = q0.y + q0.w;
    const float bx1 = q1.x, by1 = q1.y, bx2 = q1.x + q1.z, by2 = q1.y + q1.w;
    const float apa = fabsf((ax2 - ax1) * (ay2 - ay1)) + 1e-9f;  // area + eps hoisted
    const float bpa = fabsf((bx2 - bx1) * (by2 - by1)) + 1e-9f;

    float best0 = 0.0f, best1 = 0.0f;
    int   bg0 = 0, bg1 = 0;

#pragma unroll
    for (int g = 0; g < GH; ++g) {
        float4 gb = sbox[g];
        float  sa = sarea[g];
        {
            float iw = fminf(ax2, gb.z) - fmaxf(ax1, gb.x);   // unclamped
            float ih = fmaxf(fminf(ay2, gb.w) - fmaxf(ay1, gb.y), 0.0f);
            float n  = iw * ih;
            float u  = (apa + sa) - n;                        // >= eps, NaN-free
            float iou = __fdividef(n, u);
            if (iou > best0) { best0 = iou; bg0 = g; }        // strict > = first max
        }
        {
            float iw = fminf(bx2, gb.z) - fmaxf(bx1, gb.x);
            float ih = fmaxf(fminf(by2, gb.w) - fmaxf(by1, gb.y), 0.0f);
            float n  = iw * ih;
            float u  = (bpa + sa) - n;
            float iou = __fdividef(n, u);
            if (iou > best1) { best1 = iou; bg1 = g; }
        }
    }

    const int goff = zt * GH;
    {
        unsigned long long pack = ((unsigned long long)__float_as_uint(best0) << 32)
                                | (unsigned)(511 - (bg0 + goff));
        atomicMax(&g_best[(size_t)b * PP + p0], pack);
    }
    {
        unsigned long long pack = ((unsigned long long)__float_as_uint(best1) << 32)
                                | (unsigned)(511 - (bg1 + goff));
        atomicMax(&g_best[(size_t)b * PP + p1], pack);
    }
}

// ---------------------------------------------------------------------------
// K2a (round-12 formulation — rank work spread over 512 blocks):
// consume merged best (+reset for next replay), detect candidates, compute
// exact stable-sort rank for candidates only (warp-cooperative count).
// grid = (PP/256, BB), 256 threads.
// ---------------------------------------------------------------------------
__global__ __launch_bounds__(256) void k_cand(
    const float* __restrict__ pred_scores,   // [B,P]
    const int*   __restrict__ pred_classes,  // [B,P]
    const int*   __restrict__ gt_classes)    // [B,G]
{
    const int b   = blockIdx.y;
    const int tid = threadIdx.x;
    const int p   = blockIdx.x * 256 + tid;

    __shared__ float ssc[PP];   // all scores of image b

    const float4* sp = reinterpret_cast<const float4*>(pred_scores + (size_t)b * PP);
    for (int i = tid; i < PP / 4; i += 256)
        reinterpret_cast<float4*>(ssc)[i] = sp[i];
    __syncthreads();

    const size_t idx = (size_t)b * PP + p;
    unsigned long long v = g_best[idx];
    g_best[idx] = 0ULL;   // reset for next replay (this thread is sole reader)

    const int   ginv = (int)(v & 0x1FF);        // 511 - g
    const int   g    = 511 - ginv;
    const float biou = __uint_as_float((unsigned int)(v >> 32));
    const bool  cand = (biou > 0.5f) &&
                       (pred_classes[idx] == gt_classes[(size_t)b * GG + g]);

    const float ms   = ssc[p];
    const int   lane = tid & 31;
    const unsigned full = 0xFFFFFFFFu;

    unsigned int res = 0xFFFFFFFFu;
    unsigned bal = __ballot_sync(full, cand);
    while (bal) {
        int src = __ffs(bal) - 1;
        bal &= bal - 1;
        int   pc = __shfl_sync(full, p,  src);
        float sc = __shfl_sync(full, ms, src);
        int cnt = 0;
        // rank = #(q: score_q > score_p  ||  (score_q == score_p && q < p))
        for (int q = lane; q < PP; q += 32) {
            float sq = ssc[q];
            cnt += (sq > sc) || (sq == sc && q < pc);
        }
        cnt = __reduce_add_sync(full, cnt);
        if (lane == src) res = ((unsigned int)cnt << 9) | (unsigned int)ginv;
    }

    g_cand[idx] = cand ? res : 0xFFFFFFFFu;
}

// ---------------------------------------------------------------------------
// K2b: per image — compact candidates, greedy TP (min rank per gt), AP.
// Last block (ticket) computes the batch mean. grid = BB, 256 threads.
// ---------------------------------------------------------------------------
__global__ __launch_bounds__(256) void k_ap2(float* __restrict__ out)
{
    const int b   = blockIdx.x;
    const int tid = threadIdx.x;
    const int lane = tid & 31, wid = tid >> 5;

    __shared__ unsigned int  scomp[PP];
    __shared__ unsigned char stp[PP];
    __shared__ int   wsum[8];
    __shared__ float wred[8];

    // Load 8 entries each, count valid, block-scan for p-ordered compaction.
    unsigned int vals[8];
    int c = 0;
    const int base = tid * 8;
#pragma unroll
    for (int k = 0; k < 8; ++k) {
        vals[k] = g_cand[(size_t)b * PP + base + k];
        c += (vals[k] != 0xFFFFFFFFu) ? 1 : 0;
    }
    int sc = c;
    for (int o = 1; o < 32; o <<= 1) {
        int u = __shfl_up_sync(0xFFFFFFFFu, sc, o);
        if (lane >= o) sc += u;
    }
    if (lane == 31) wsum[wid] = sc;
    __syncthreads();
    if (wid == 0 && lane < 8) {
        int u = wsum[lane];
        for (int o = 1; o < 8; o <<= 1) {
            int w = __shfl_up_sync(0xFFu, u, o);
            if (lane >= o) u += w;
        }
        wsum[lane] = u;
    }
    __syncthreads();
    int off = (sc - c) + (wid > 0 ? wsum[wid - 1] : 0);
    const int n = wsum[7];
#pragma unroll
    for (int k = 0; k < 8; ++k)
        if (vals[k] != 0xFFFFFFFFu) scomp[off++] = vals[k];
    __syncthreads();

    // TP iff no other candidate with same gt and smaller rank.
    // packed = (rank<<9)|ginv: same ginv -> same gt; smaller packed -> smaller rank.
    for (int i = tid; i < n; i += 256) {
        unsigned int v = scomp[i];
        int tp = 1;
        for (int j = 0; j < n; ++j) {
            unsigned int w = scomp[j];
            if (w < v && !((w ^ v) & 0x1FFu)) tp = 0;
        }
        stp[i] = (unsigned char)tp;
    }
    __syncthreads();

    // AP terms. For a tp at global rank r (k = r+1), j = 1 + #(tps with rank < r):
    //   term = 0.5 * ( j/k + (k==1 ? 1 : (j-1)/(k-1)) );  AP = sum(term)/G.
    float acc = 0.0f;
    for (int i = tid; i < n; i += 256) {
        if (!stp[i]) continue;
        unsigned int v = scomp[i];
        unsigned int r = v >> 9;
        int j = 1;
        for (int m = 0; m < n; ++m)
            j += (stp[m] && (scomp[m] >> 9) < r) ? 1 : 0;
        float kk = (float)(r + 1);
        float pj = (float)j;
        float prev = (r == 0) ? 1.0f : (pj - 1.0f) / (kk - 1.0f);
        acc += 0.5f * (pj / kk + prev);
    }

    // Deterministic block reduce.
    for (int o = 16; o > 0; o >>= 1) acc += __shfl_down_sync(0xFFFFFFFFu, acc, o);
    if (lane == 0) wred[wid] = acc;
    __syncthreads();
    if (tid == 0) {
        float u = 0.0f;
#pragma unroll
        for (int w = 0; w < 8; ++w) u += wred[w];
        g_ap[b] = u / (float)GG;

        // Ticket: last block computes the mean. atomicInc wraps 63 -> 0, so the
        // counter self-resets for every graph replay.
        __threadfence();
        unsigned old = atomicInc(&g_ticket, BB - 1);
        if (old == BB - 1) {
            float s = 0.0f;
#pragma unroll
            for (int i = 0; i < BB; ++i) s += g_ap[i];   // fixed order
            out[0] = s * (1.0f / (float)BB);
        }
    }
}

// ---------------------------------------------------------------------------
extern "C" void kernel_launch(void* const* d_in, const int* in_sizes, int n_in,
                              void* d_out, int out_size)
{
    const float* pred_boxes   = (const float*)d_in[0];
    const float* pred_scores  = (const float*)d_in[1];
    const int*   pred_classes = (const int*)d_in[2];
    const float* gt_boxes     = (const float*)d_in[3];
    const int*   gt_classes   = (const int*)d_in[4];
    float* out = (float*)d_out;

    dim3 g1(PP / 512, BB, NZ);
    k_bestiou<<<g1, 256>>>(pred_boxes, gt_boxes);
    dim3 g2(PP / 256, BB);
    k_cand<<<g2, 256>>>(pred_scores, pred_classes, gt_classes);
    k_ap2<<<BB, 256>>>(out);
}

// round 15
// speedup vs baseline: 1.0692x; 1.0016x over previous
#include <cuda_runtime.h>
#include <stdint.h>

// Problem shapes (fixed by the dataset).
#define BB 64
#define PP 2048
#define GG 512
#define NZ 16
#define GH (GG / NZ)    // 32 gts per tile

// Merged best per (image, pred): (iou_bits<<32) | (511 - g). Zero-initialized;
// K2 resets each element after consuming it (replay-safe).
__device__ unsigned long long g_best[BB * PP];
// Dense per (image, pred): (rank<<9) | ginv. 0xFFFFFFFF = not a candidate.
__device__ unsigned int g_cand[BB * PP];
__device__ float g_ap[BB];
__device__ unsigned int g_ticket_img[BB];  // per-image last-block tickets (wrap 7->0)
__device__ unsigned int g_ticket;          // global mean ticket (wrap 63->0)

// ---------------------------------------------------------------------------
// K1 (measured 48.1us — unchanged): per (image, pred, gt-tile) first-max
// argmax_g IoU + exact max value, merged globally via u64 atomicMax
// (iou desc, tie -> lower g). 256 threads, 2 preds/thread, 32 gts in smem.
// grid = (PP/512, BB, NZ). best init 0: negative ious (unclamped iw) never
// update; all-nonpositive tiles pack (0, tile-g0) and the merge resolves
// them to g = 0, matching the reference argmax of an all-zero row.
// ---------------------------------------------------------------------------
__global__ __launch_bounds__(256) void k_bestiou(
    const float* __restrict__ pred_boxes,   // [B,P,4] xywh
    const float* __restrict__ gt_boxes)     // [B,G,4] xywh
{
    const int b  = blockIdx.y;
    const int zt = blockIdx.z;
    const int p0 = blockIdx.x * 512 + threadIdx.x;
    const int p1 = p0 + 256;

    __shared__ float4 sbox[GH];   // x1,y1,x2,y2
    __shared__ float  sarea[GH];  // exact area

    const float4* gbp = reinterpret_cast<const float4*>(
        gt_boxes + ((size_t)b * GG + (size_t)zt * GH) * 4);
    if (threadIdx.x < GH) {
        float4 v = gbp[threadIdx.x];
        float x2 = v.x + v.z;
        float y2 = v.y + v.w;
        sbox[threadIdx.x]  = make_float4(v.x, v.y, x2, y2);
        sarea[threadIdx.x] = fabsf((x2 - v.x) * (y2 - v.y));
    }
    __syncthreads();

    const float4* pbp = reinterpret_cast<const float4*>(pred_boxes + (size_t)b * PP * 4);
    float4 q0 = pbp[p0];
    float4 q1 = pbp[p1];
    const float ax1 = q0.x, ay1 = q0.y, ax2 = q0.x + q0.z, ay2 = q0.y + q0.w;
    const float bx1 = q1.x, by1 = q1.y, bx2 = q1.x + q1.z, by2 = q1.y + q1.w;
    const float apa = fabsf((ax2 - ax1) * (ay2 - ay1)) + 1e-9f;  // area + eps hoisted
    const float bpa = fabsf((bx2 - bx1) * (by2 - by1)) + 1e-9f;

    float best0 = 0.0f, best1 = 0.0f;
    int   bg0 = 0, bg1 = 0;

#pragma unroll
    for (int g = 0; g < GH; ++g) {
        float4 gb = sbox[g];
        float  sa = sarea[g];
        {
            float iw = fminf(ax2, gb.z) - fmaxf(ax1, gb.x);   // unclamped
            float ih = fmaxf(fminf(ay2, gb.w) - fmaxf(ay1, gb.y), 0.0f);
            float n  = iw * ih;
            float u  = (apa + sa) - n;                        // >= eps, NaN-free
            float iou = __fdividef(n, u);
            if (iou > best0) { best0 = iou; bg0 = g; }        // strict > = first max
        }
        {
            float iw = fminf(bx2, gb.z) - fmaxf(bx1, gb.x);
            float ih = fmaxf(fminf(by2, gb.w) - fmaxf(by1, gb.y), 0.0f);
            float n  = iw * ih;
            float u  = (bpa + sa) - n;
            float iou = __fdividef(n, u);
            if (iou > best1) { best1 = iou; bg1 = g; }
        }
    }

    const int goff = zt * GH;
    {
        unsigned long long pack = ((unsigned long long)__float_as_uint(best0) << 32)
                                | (unsigned)(511 - (bg0 + goff));
        atomicMax(&g_best[(size_t)b * PP + p0], pack);
    }
    {
        unsigned long long pack = ((unsigned long long)__float_as_uint(best1) << 32)
                                | (unsigned)(511 - (bg1 + goff));
        atomicMax(&g_best[(size_t)b * PP + p1], pack);
    }
}

// ---------------------------------------------------------------------------
// K2 (fused K2a + per-image last-block K2b):
// Phase 1 (all 8 blocks of image b): consume g_best (+reset), detect
//   candidates, exact stable-sort rank (warp-cooperative), write g_cand.
// Phase 2 (last-arriving block per image, via wrap-reset ticket): compact
//   candidates, greedy TP, AP; last image (global ticket) computes the mean.
// grid = (PP/256, BB), 256 threads. smem reused across phases (union).
// ---------------------------------------------------------------------------
__global__ __launch_bounds__(256) void k_cand_ap(
    const float* __restrict__ pred_scores,   // [B,P]
    const int*   __restrict__ pred_classes,  // [B,P]
    const int*   __restrict__ gt_classes,    // [B,G]
    float* __restrict__ out)
{
    const int b   = blockIdx.y;
    const int tid = threadIdx.x;
    const int lane = tid & 31, wid = tid >> 5;
    const unsigned full = 0xFFFFFFFFu;

    // Phase 1 uses sbuf as float scores; phase 2 reuses it as compacted keys.
    __shared__ unsigned int  sbuf[PP];
    __shared__ unsigned char stp[PP];
    __shared__ int   wsum[8];
    __shared__ float wred[8];
    __shared__ int   slast;

    float* ssc = reinterpret_cast<float*>(sbuf);

    // ---- Phase 1: candidate detection + exact rank ----
    const float4* sp = reinterpret_cast<const float4*>(pred_scores + (size_t)b * PP);
    for (int i = tid; i < PP / 4; i += 256)
        reinterpret_cast<float4*>(ssc)[i] = sp[i];
    __syncthreads();

    const int p = blockIdx.x * 256 + tid;
    const size_t idx = (size_t)b * PP + p;
    unsigned long long v = g_best[idx];
    g_best[idx] = 0ULL;   // reset for next replay (this thread is sole reader)

    const int   ginv = (int)(v & 0x1FF);        // 511 - g
    const int   g    = 511 - ginv;
    const float biou = __uint_as_float((unsigned int)(v >> 32));
    const bool  cand = (biou > 0.5f) &&
                       (pred_classes[idx] == gt_classes[(size_t)b * GG + g]);
    const float ms = ssc[p];

    unsigned int res = 0xFFFFFFFFu;
    unsigned bal = __ballot_sync(full, cand);
    while (bal) {
        int src = __ffs(bal) - 1;
        bal &= bal - 1;
        int   pc = __shfl_sync(full, p,  src);
        float sc = __shfl_sync(full, ms, src);
        int cnt = 0;
        // rank = #(q: score_q > score_p  ||  (score_q == score_p && q < p))
        for (int q = lane; q < PP; q += 32) {
            float sq = ssc[q];
            cnt += (sq > sc) || (sq == sc && q < pc);
        }
        cnt = __reduce_add_sync(full, cnt);
        if (lane == src) res = ((unsigned int)cnt << 9) | (unsigned int)ginv;
    }
    g_cand[idx] = cand ? res : 0xFFFFFFFFu;

    // ---- Handoff: last block of this image proceeds to phase 2 ----
    __threadfence();
    __syncthreads();   // also: ssc (sbuf) is dead from here on
    if (tid == 0) {
        unsigned old = atomicInc(&g_ticket_img[b], (PP / 256) - 1);  // wraps 7->0
        slast = (old == (PP / 256) - 1) ? 1 : 0;
    }
    __syncthreads();
    if (!slast) return;

    // ---- Phase 2: compact, greedy TP, AP (this block only) ----
    unsigned int vals[8];
    int c = 0;
    const int base = tid * 8;
#pragma unroll
    for (int k = 0; k < 8; ++k) {
        vals[k] = g_cand[(size_t)b * PP + base + k];
        c += (vals[k] != 0xFFFFFFFFu) ? 1 : 0;
    }
    int sc2 = c;
    for (int o = 1; o < 32; o <<= 1) {
        int u = __shfl_up_sync(full, sc2, o);
        if (lane >= o) sc2 += u;
    }
    if (lane == 31) wsum[wid] = sc2;
    __syncthreads();
    if (wid == 0 && lane < 8) {
        int u = wsum[lane];
        for (int o = 1; o < 8; o <<= 1) {
            int w = __shfl_up_sync(0xFFu, u, o);
            if (lane >= o) u += w;
        }
        wsum[lane] = u;
    }
    __syncthreads();
    int off = (sc2 - c) + (wid > 0 ? wsum[wid - 1] : 0);
    const int n = wsum[7];
#pragma unroll
    for (int k = 0; k < 8; ++k)
        if (vals[k] != 0xFFFFFFFFu) sbuf[off++] = vals[k];
    __syncthreads();

    // TP iff no other candidate with same gt and smaller rank.
    // packed = (rank<<9)|ginv: same ginv -> same gt; smaller packed -> smaller rank.
    for (int i = tid; i < n; i += 256) {
        unsigned int vv = sbuf[i];
        int tp = 1;
        for (int j = 0; j < n; ++j) {
            unsigned int w = sbuf[j];
            if (w < vv && !((w ^ vv) & 0x1FFu)) tp = 0;
        }
        stp[i] = (unsigned char)tp;
    }
    __syncthreads();

    // AP terms. For a tp at global rank r (k = r+1), j = 1 + #(tps with rank < r):
    //   term = 0.5 * ( j/k + (k==1 ? 1 : (j-1)/(k-1)) );  AP = sum(term)/G.
    float acc = 0.0f;
    for (int i = tid; i < n; i += 256) {
        if (!stp[i]) continue;
        unsigned int vv = sbuf[i];
        unsigned int r = vv >> 9;
        int j = 1;
        for (int m = 0; m < n; ++m)
            j += (stp[m] && (sbuf[m] >> 9) < r) ? 1 : 0;
        float kk = (float)(r + 1);
        float pj = (float)j;
        float prev = (r == 0) ? 1.0f : (pj - 1.0f) / (kk - 1.0f);
        acc += 0.5f * (pj / kk + prev);
    }

    // Deterministic block reduce.
    for (int o = 16; o > 0; o >>= 1) acc += __shfl_down_sync(full, acc, o);
    if (lane == 0) wred[wid] = acc;
    __syncthreads();
    if (tid == 0) {
        float u = 0.0f;
#pragma unroll
        for (int w = 0; w < 8; ++w) u += wred[w];
        g_ap[b] = u / (float)GG;

        // Global ticket: last image computes the mean (wraps 63 -> 0).
        __threadfence();
        unsigned old = atomicInc(&g_ticket, BB - 1);
        if (old == BB - 1) {
            float s = 0.0f;
#pragma unroll
            for (int i = 0; i < BB; ++i) s += g_ap[i];   // fixed order
            out[0] = s * (1.0f / (float)BB);
        }
    }
}

// ---------------------------------------------------------------------------
extern "C" void kernel_launch(void* const* d_in, const int* in_sizes, int n_in,
                              void* d_out, int out_size)
{
    const float* pred_boxes   = (const float*)d_in[0];
    const float* pred_scores  = (const float*)d_in[1];
    const int*   pred_classes = (const int*)d_in[2];
    const float* gt_boxes     = (const float*)d_in[3];
    const int*   gt_classes   = (const int*)d_in[4];
    float* out = (float*)d_out;

    dim3 g1(PP / 512, BB, NZ);
    k_bestiou<<<g1, 256>>>(pred_boxes, gt_boxes);
    dim3 g2(PP / 256, BB);
    k_cand_ap<<<g2, 256>>>(pred_scores, pred_classes, gt_classes, out);
}